// round 4
// baseline (speedup 1.0000x reference)
#include <cuda_runtime.h>

// SparseBiasDiagUnfolder — warp handles 4 window-rows (R3 pattern + MLP=4).
//   adj: (B=2, N=2048, N=2048, F=16) fp32; starts 0,4,...,2040 (511);
//   out (B, 511, 56*16).
//
// Row r = (bs, ii): 512B contiguous in adj. 4 consecutive rows always share
// bs (rows-per-bs = 8, rows-per-warp = 4), so the /511 decompose runs once
// per warp. Loads: 4 independent, fully coalesced 512B LDG.128 batched up
// front. Stores: 28 active lanes per row, contiguous 448B run each.

namespace {
constexpr int N        = 2048;
constexpr int NSTARTS  = 511;
constexpr int NROWS    = 2 * NSTARTS * 8;   // 8176
constexpr int ROWS_PER_WARP = 4;
constexpr int THREADS  = 128;               // 4 warps/block
constexpr int NWARPS   = NROWS / ROWS_PER_WARP;        // 2044
constexpr int BLOCKS   = NWARPS / 4;                   // 511 (exact)
}

__global__ void __launch_bounds__(THREADS)
sparse_diag_unfold_kernel(const float4* __restrict__ adj, float4* __restrict__ out)
{
    const int gt   = blockIdx.x * THREADS + threadIdx.x;
    const int w    = gt >> 5;                 // warp id, 0..2043
    const int lane = gt & 31;

    // warp w covers rows [4w, 4w+4) -> same bs group
    const int bs      = w >> 1;               // b*511 + s
    const int ii_base = (w & 1) * 4;          // 0 or 4
    const int s  = bs % NSTARTS;
    const int b  = bs / NSTARTS;

    // float4 base index of row (bs, ii_base):
    // (b*N*N + 4s*(N+1) + ii*N) floats*16 -> /4
    const long base0 = ((long)b * N * N
                      + (long)(4 * s) * (N + 1)
                      + (long)ii_base * N) * 4;

    const int jj = lane >> 2;
    const int v  = lane & 3;

    // Batch 4 independent coalesced 512B loads (MLP_p1 = 4).
    float4 vals[ROWS_PER_WARP];
    #pragma unroll
    for (int k = 0; k < ROWS_PER_WARP; k++)
        vals[k] = adj[base0 + (long)k * (N * 4) + lane];

    const long out_base = (long)bs * 56 * 4;
    #pragma unroll
    for (int k = 0; k < ROWS_PER_WARP; k++) {
        const int ii = ii_base + k;
        if (jj != ii) {
            const int pos = ii * 7 + jj - (jj > ii);   // 0..55
            out[out_base + pos * 4 + v] = vals[k];
        }
    }
}

extern "C" void kernel_launch(void* const* d_in, const int* in_sizes, int n_in,
                              void* d_out, int out_size)
{
    const float4* adj = (const float4*)d_in[0];
    float4* out = (float4*)d_out;
    sparse_diag_unfold_kernel<<<BLOCKS, THREADS>>>(adj, out);
}

// round 5
// speedup vs baseline: 1.0488x; 1.0488x over previous
#include <cuda_runtime.h>

// SparseBiasDiagUnfolder — one-wave configuration (146 blocks = 1 CTA/SM-ish,
// 448 threads = 14 warps; 2044 warps total, each handling 4 window rows).
//
//   adj: (B=2, N=2048, N=2048, F=16) fp32; starts 0,4,...,2040 (511);
//   out (B, 511, 56*16).
//
// Warp w covers rows [4w, 4w+4): same bs = b*511+s group (8 rows per bs,
// 4 rows per warp). Each row is 512B contiguous in adj -> 4 independent
// fully-coalesced LDG.128 batched up front (MLP_p1=4). Stores: per row,
// 28 active lanes write a contiguous 448B run (diagonal chunk dropped,
// positions repacked pos = ii*7 + jj - (jj>ii)).

namespace {
constexpr int N        = 2048;
constexpr int NSTARTS  = 511;
constexpr int NROWS    = 2 * NSTARTS * 8;        // 8176
constexpr int ROWS_PER_WARP = 4;
constexpr int NWARPS   = NROWS / ROWS_PER_WARP;  // 2044
constexpr int WARPS_PER_BLOCK = 14;
constexpr int THREADS  = WARPS_PER_BLOCK * 32;   // 448
constexpr int BLOCKS   = NWARPS / WARPS_PER_BLOCK;  // 146 (exact)
}

__global__ void __launch_bounds__(THREADS)
sparse_diag_unfold_kernel(const float4* __restrict__ adj, float4* __restrict__ out)
{
    const int gt   = blockIdx.x * THREADS + threadIdx.x;
    const int w    = gt >> 5;                 // warp id, 0..2043
    const int lane = gt & 31;

    const int bs      = w >> 1;               // b*511 + s
    const int ii_base = (w & 1) * 4;          // 0 or 4
    const int s  = bs % NSTARTS;
    const int b  = bs / NSTARTS;

    // float4 base index of row (bs, ii_base)
    const long base0 = ((long)b * N * N
                      + (long)(4 * s) * (N + 1)
                      + (long)ii_base * N) * 4;

    const int jj = lane >> 2;
    const int v  = lane & 3;

    // 4 independent coalesced 512B loads, batched (MLP_p1 = 4).
    float4 vals[ROWS_PER_WARP];
    #pragma unroll
    for (int k = 0; k < ROWS_PER_WARP; k++)
        vals[k] = adj[base0 + (long)k * (N * 4) + lane];

    const long out_base = (long)bs * 56 * 4;
    #pragma unroll
    for (int k = 0; k < ROWS_PER_WARP; k++) {
        const int ii = ii_base + k;
        if (jj != ii) {
            const int pos = ii * 7 + jj - (jj > ii);   // 0..55
            out[out_base + pos * 4 + v] = vals[k];
        }
    }
}

extern "C" void kernel_launch(void* const* d_in, const int* in_sizes, int n_in,
                              void* d_out, int out_size)
{
    const float4* adj = (const float4*)d_in[0];
    float4* out = (float4*)d_out;
    sparse_diag_unfold_kernel<<<BLOCKS, THREADS>>>(adj, out);
}